// round 1
// baseline (speedup 1.0000x reference)
#include <cuda_runtime.h>
#include <math.h>

// Problem dims (fixed by the dataset)
#define B 1024
#define S 64
#define E 256
#define H 512
#define V 128
#define C 32

#define BT   8           // batch rows per CTA
#define NBLK (B / BT)    // 128 CTAs
#define THR  256         // threads per CTA; each thread owns h-dims (tid, tid+256)

// Scratch (no allocations allowed -> __device__ globals)
__device__ float g_P[V * H];      // emb @ W_ih^T + b_ih + b_hh  (256 KB)
__device__ float g_last[B * H];   // h at t = len-1, per original row (2 MB)
__device__ int   g_sidx[B];       // batch indices sorted by length
__device__ int   g_slen[B];       // lengths, sorted ascending

// ---------------------------------------------------------------------------
// Kernel 1: P[v][h] = sum_e emb[v,e] * W_ih[h,e] + b_ih[h] + b_hh[h]
// grid = V (128), block = H (512)
// ---------------------------------------------------------------------------
__global__ void precompute_P(const float* __restrict__ emb,
                             const float* __restrict__ W_ih,
                             const float* __restrict__ b_ih,
                             const float* __restrict__ b_hh) {
    __shared__ float es[E];
    const int v = blockIdx.x;
    const int h = threadIdx.x;            // 0..511
    if (h < E) es[h] = emb[v * E + h];
    __syncthreads();

    float acc = b_ih[h] + b_hh[h];
    const float4* w  = reinterpret_cast<const float4*>(W_ih + h * E);
    const float4* e4 = reinterpret_cast<const float4*>(es);
#pragma unroll 8
    for (int i = 0; i < E / 4; i++) {
        float4 a = e4[i], b = w[i];
        acc += a.x * b.x + a.y * b.y + a.z * b.z + a.w * b.w;
    }
    g_P[v * H + h] = acc;
}

// ---------------------------------------------------------------------------
// Kernel 2: counting-style rank sort of rows by length (stable).
// Single block of B=1024 threads; O(B^2) compares in shared ~ a few us.
// ---------------------------------------------------------------------------
__global__ void sort_by_len(const int* __restrict__ lens) {
    __shared__ int sl[B];
    const int i = threadIdx.x;
    sl[i] = lens[i];
    __syncthreads();
    const int my = sl[i];
    int rank = 0;
#pragma unroll 8
    for (int j = 0; j < B; j++) {
        int lj = sl[j];
        rank += (lj < my) || (lj == my && j < i);
    }
    g_sidx[rank] = i;
    g_slen[rank] = my;
}

// ---------------------------------------------------------------------------
// Kernel 3: persistent RNN. Each CTA owns 8 sorted batch rows, runs the full
// time loop to its tile's max length. Input contribution is a gather from g_P.
// h state lives in shared [8][512]; W_hh streamed from L2 each step.
// ---------------------------------------------------------------------------
__global__ void __launch_bounds__(THR) rnn_kernel(const int*   __restrict__ x_in,
                                                  const float* __restrict__ W_hh) {
    __shared__ float4 h4[BT * (H / 4)];        // 16 KB, [b][k/4]
    __shared__ int orig[BT], slen[BT], xi[BT];

    const int tid  = threadIdx.x;
    const int base = blockIdx.x * BT;

    if (tid < BT) {
        orig[tid] = g_sidx[base + tid];
        slen[tid] = g_slen[base + tid];
    }
    for (int i = tid; i < BT * (H / 4); i += THR)
        h4[i] = make_float4(0.f, 0.f, 0.f, 0.f);
    __syncthreads();

    int tmax = 0;
#pragma unroll
    for (int b = 0; b < BT; b++) tmax = max(tmax, slen[b]);

    const int h0 = tid;
    const int h1 = tid + THR;
    const float4* W0 = reinterpret_cast<const float4*>(W_hh + h0 * H);
    const float4* W1 = reinterpret_cast<const float4*>(W_hh + h1 * H);
    float* hs = reinterpret_cast<float*>(h4);

    for (int t = 0; t < tmax; t++) {
        if (tid < BT) xi[tid] = x_in[orig[tid] * S + t];
        __syncthreads();   // xi ready; prev-step h4 writes visible

        // init accumulators from the input-path table
        float a0[BT], a1[BT];
#pragma unroll
        for (int b = 0; b < BT; b++) {
            const float* Pr = g_P + xi[b] * H;
            a0[b] = Pr[h0];
            a1[b] = Pr[h1];
        }

        // a += W_hh[h,:] . h_prev[b,:]
#pragma unroll 2
        for (int kk = 0; kk < H / 4; kk++) {
            float4 w0 = W0[kk];
            float4 w1 = W1[kk];
#pragma unroll
            for (int b = 0; b < BT; b++) {
                float4 hv = h4[b * (H / 4) + kk];
                a0[b] += w0.x * hv.x + w0.y * hv.y + w0.z * hv.z + w0.w * hv.w;
                a1[b] += w1.x * hv.x + w1.y * hv.y + w1.z * hv.z + w1.w * hv.w;
            }
        }
        __syncthreads();   // all reads of h4 complete before overwrite

#pragma unroll
        for (int b = 0; b < BT; b++) {
            float v0 = tanhf(a0[b]);
            float v1 = tanhf(a1[b]);
            hs[b * H + h0] = v0;
            hs[b * H + h1] = v1;
            if (t == slen[b] - 1) {
                g_last[orig[b] * H + h0] = v0;
                g_last[orig[b] * H + h1] = v1;
            }
        }
        // no trailing sync needed: next iteration's first __syncthreads()
        // orders these writes before the next reads.
    }
}

// ---------------------------------------------------------------------------
// Kernel 4: MLP head. hidden = relu(last @ W1^T + b1); out = hidden @ W2^T + b2.
// Same [8,512]x[512,512] structure as one RNN step, then a tiny 512->32 GEMM.
// ---------------------------------------------------------------------------
__global__ void __launch_bounds__(THR) mlp_kernel(const float* __restrict__ W1w,
                                                  const float* __restrict__ b1,
                                                  const float* __restrict__ W2w,
                                                  const float* __restrict__ b2,
                                                  float* __restrict__ out) {
    __shared__ float4 h4[BT * (H / 4)];
    const int tid  = threadIdx.x;
    const int base = blockIdx.x * BT;

    // load 8 rows of g_last (unsorted / original order)
    const float4* src = reinterpret_cast<const float4*>(g_last + base * H);
    for (int i = tid; i < BT * (H / 4); i += THR) h4[i] = src[i];
    __syncthreads();

    const int h0 = tid;
    const int h1 = tid + THR;
    float a0[BT], a1[BT];
#pragma unroll
    for (int b = 0; b < BT; b++) { a0[b] = b1[h0]; a1[b] = b1[h1]; }

    const float4* Wr0 = reinterpret_cast<const float4*>(W1w + h0 * H);
    const float4* Wr1 = reinterpret_cast<const float4*>(W1w + h1 * H);
#pragma unroll 2
    for (int kk = 0; kk < H / 4; kk++) {
        float4 w0 = Wr0[kk];
        float4 w1 = Wr1[kk];
#pragma unroll
        for (int b = 0; b < BT; b++) {
            float4 hv = h4[b * (H / 4) + kk];
            a0[b] += w0.x * hv.x + w0.y * hv.y + w0.z * hv.z + w0.w * hv.w;
            a1[b] += w1.x * hv.x + w1.y * hv.y + w1.z * hv.z + w1.w * hv.w;
        }
    }
    __syncthreads();

    float* hs = reinterpret_cast<float*>(h4);
#pragma unroll
    for (int b = 0; b < BT; b++) {
        hs[b * H + h0] = fmaxf(a0[b], 0.f);
        hs[b * H + h1] = fmaxf(a1[b], 0.f);
    }
    __syncthreads();

    // logits: 8 rows x 32 classes = 256 outputs, one per thread
    const int b = tid >> 5;
    const int c = tid & 31;
    float acc = b2[c];
    const float4* w2 = reinterpret_cast<const float4*>(W2w + c * H);
    const float4* hb = &h4[b * (H / 4)];
#pragma unroll 4
    for (int kk = 0; kk < H / 4; kk++) {
        float4 w = w2[kk], hv = hb[kk];
        acc += w.x * hv.x + w.y * hv.y + w.z * hv.z + w.w * hv.w;
    }
    out[(base + b) * C + c] = acc;
}

// ---------------------------------------------------------------------------
extern "C" void kernel_launch(void* const* d_in, const int* in_sizes, int n_in,
                              void* d_out, int out_size) {
    const int*   x_in   = (const int*)  d_in[0];
    const int*   x_lens = (const int*)  d_in[1];
    const float* emb    = (const float*)d_in[2];
    const float* W_ih   = (const float*)d_in[3];
    const float* b_ih   = (const float*)d_in[4];
    const float* W_hh   = (const float*)d_in[5];
    const float* b_hh   = (const float*)d_in[6];
    const float* W1w    = (const float*)d_in[7];
    const float* b1     = (const float*)d_in[8];
    const float* W2w    = (const float*)d_in[9];
    const float* b2     = (const float*)d_in[10];
    float* out = (float*)d_out;

    precompute_P<<<V, H>>>(emb, W_ih, b_ih, b_hh);
    sort_by_len<<<1, B>>>(x_lens);
    rnn_kernel<<<NBLK, THR>>>(x_in, W_hh);
    mlp_kernel<<<NBLK, THR>>>(W1w, b1, W2w, b2, out);
}

// round 2
// speedup vs baseline: 2.2555x; 2.2555x over previous
#include <cuda_runtime.h>
#include <math.h>

// Problem dims (fixed by the dataset)
#define B 1024
#define S 64
#define E 256
#define H 512
#define V 128
#define C 32

#define BT   8           // batch rows per CTA tile
#define BP   4           // batch pairs (f32x2 packs 2 batch rows)
#define HP   (H / 2)     // h-dim pairs per row (thread owns h = 2*tid, 2*tid+1)
#define NBLK (B / BT)    // 128 CTAs
#define THR  256

// Scratch (no allocations allowed -> __device__ globals)
__device__ float g_P[V * H];       // emb @ W_ih^T + b_ih + b_hh   (256 KB)
__device__ float g_WT[H * H];      // W_hh transposed: [k][h]      (1 MB)
__device__ float g_W1T[H * H];     // W1 transposed:   [k][h]      (1 MB)
__device__ float g_W2T[H * C];     // W2 transposed:   [k][c]      (64 KB)
__device__ float g_last[B * H];    // h at t = len-1, original row order (2 MB)
__device__ int   g_sidx[B];
__device__ int   g_slen[B];

// ---------------------------------------------------------------------------
// f32x2 helpers (packed fp32 pair FMA — sm_103a FFMA2 path)
// ---------------------------------------------------------------------------
__device__ __forceinline__ unsigned long long pk2(float x, float y) {
    unsigned long long r;
    asm("mov.b64 %0, {%1, %2};" : "=l"(r) : "f"(x), "f"(y));
    return r;
}
__device__ __forceinline__ void upk2(unsigned long long v, float& x, float& y) {
    asm("mov.b64 {%0, %1}, %2;" : "=f"(x), "=f"(y) : "l"(v));
}
__device__ __forceinline__ void fma2(unsigned long long& d, unsigned long long a,
                                     unsigned long long b) {
    asm("fma.rn.f32x2 %0, %1, %2, %3;" : "=l"(d) : "l"(a), "l"(b), "l"(d));
}

// ---------------------------------------------------------------------------
// Kernel 1: P[v][h] = sum_e emb[v,e] * W_ih[h,e] + b_ih[h] + b_hh[h]
// ---------------------------------------------------------------------------
__global__ void precompute_P(const float* __restrict__ emb,
                             const float* __restrict__ W_ih,
                             const float* __restrict__ b_ih,
                             const float* __restrict__ b_hh) {
    __shared__ float es[E];
    const int v = blockIdx.x;
    const int h = threadIdx.x;
    if (h < E) es[h] = emb[v * E + h];
    __syncthreads();

    float acc = b_ih[h] + b_hh[h];
    const float4* w  = reinterpret_cast<const float4*>(W_ih + h * E);
    const float4* e4 = reinterpret_cast<const float4*>(es);
#pragma unroll 8
    for (int i = 0; i < E / 4; i++) {
        float4 a = e4[i], b = w[i];
        acc += a.x * b.x + a.y * b.y + a.z * b.z + a.w * b.w;
    }
    g_P[v * H + h] = acc;
}

// ---------------------------------------------------------------------------
// Kernel 2: stable rank sort of rows by length
// ---------------------------------------------------------------------------
__global__ void sort_by_len(const int* __restrict__ lens) {
    __shared__ int sl[B];
    const int i = threadIdx.x;
    sl[i] = lens[i];
    __syncthreads();
    const int my = sl[i];
    int rank = 0;
#pragma unroll 8
    for (int j = 0; j < B; j++) {
        int lj = sl[j];
        rank += (lj < my) || (lj == my && j < i);
    }
    g_sidx[rank] = i;
    g_slen[rank] = my;
}

// ---------------------------------------------------------------------------
// Kernel 3: transpose W_hh, W1 (512x512) and W2 (32x512) -> k-major
// ---------------------------------------------------------------------------
__global__ void transpose_all(const float* __restrict__ W_hh,
                              const float* __restrict__ W1,
                              const float* __restrict__ W2) {
    int idx = blockIdx.x * blockDim.x + threadIdx.x;
    if (idx < H * H) {
        int h = idx >> 9, k = idx & (H - 1);
        g_WT[k * H + h] = W_hh[idx];
    } else if (idx < 2 * H * H) {
        int j = idx - H * H;
        int h = j >> 9, k = j & (H - 1);
        g_W1T[k * H + h] = W1[j];
    } else {
        int j = idx - 2 * H * H;
        if (j < C * H) {
            int c = j >> 9, k = j & (H - 1);
            g_W2T[k * C + c] = W2[j];
        }
    }
}

// ---------------------------------------------------------------------------
// Shared GEMM-step helpers.
// hT (shared): [k][2] ulonglong2 — 8 batch values per k packed as 4 f32x2 pairs.
// WT (global, ull view): [k][HP] — thread tid owns h-pair (2*tid, 2*tid+1).
// acc a0 (h=2*tid) and a1 (h=2*tid+1): 4 batch-pair f32x2 accumulators each.
// ---------------------------------------------------------------------------
__device__ __forceinline__ void load8(const unsigned long long* __restrict__ WTu,
                                      int k, unsigned long long w[8]) {
#pragma unroll
    for (int j = 0; j < 8; j++) w[j] = __ldg(WTu + (unsigned)(k + j) * HP);
}

__device__ __forceinline__ void compute8(const ulonglong2* __restrict__ hT, int k0,
                                         const unsigned long long w[8],
                                         unsigned long long a0[BP],
                                         unsigned long long a1[BP]) {
#pragma unroll
    for (int j = 0; j < 8; j++) {
        ulonglong2 hA = hT[(k0 + j) * 2];
        ulonglong2 hB = hT[(k0 + j) * 2 + 1];
        float wl, wh;
        upk2(w[j], wl, wh);
        unsigned long long s0 = pk2(wl, wl);
        unsigned long long s1 = pk2(wh, wh);
        fma2(a0[0], hA.x, s0); fma2(a0[1], hA.y, s0);
        fma2(a0[2], hB.x, s0); fma2(a0[3], hB.y, s0);
        fma2(a1[0], hA.x, s1); fma2(a1[1], hA.y, s1);
        fma2(a1[2], hB.x, s1); fma2(a1[3], hB.y, s1);
    }
}

// full K=512 loop, double-buffered 8-deep W prefetch
__device__ __forceinline__ void gemm_k512(const unsigned long long* __restrict__ WTu,
                                          const ulonglong2* __restrict__ hT,
                                          unsigned long long a0[BP],
                                          unsigned long long a1[BP]) {
    unsigned long long wA[8], wB[8];
    load8(WTu, 0, wA);
#pragma unroll 1
    for (int k0 = 0; k0 < H; k0 += 16) {
        load8(WTu, k0 + 8, wB);
        compute8(hT, k0, wA, a0, a1);
        int kn = (k0 + 16 < H) ? k0 + 16 : 0;   // wrap on last iter (harmless)
        load8(WTu, kn, wA);
        compute8(hT, k0 + 8, wB, a0, a1);
    }
}

// ---------------------------------------------------------------------------
// Kernel 4: persistent RNN. CTA owns 8 sorted rows; h state transposed in smem.
// ---------------------------------------------------------------------------
__global__ void __launch_bounds__(THR) rnn_kernel(const int* __restrict__ x_in) {
    __shared__ ulonglong2 hT[H * 2];            // [k][2] -> 16 KB
    __shared__ int orig[BT], slen[BT], xi[BT];

    const int tid  = threadIdx.x;
    const int base = blockIdx.x * BT;

    if (tid < BT) {
        orig[tid] = g_sidx[base + tid];
        slen[tid] = g_slen[base + tid];
    }
    for (int i = tid; i < H * 2; i += THR) hT[i] = make_ulonglong2(0ull, 0ull);
    __syncthreads();

    int tmax = 0;
#pragma unroll
    for (int b = 0; b < BT; b++) tmax = max(tmax, slen[b]);

    const unsigned long long* WTu =
        reinterpret_cast<const unsigned long long*>(g_WT) + tid;

    for (int t = 0; t < tmax; t++) {
        if (tid < BT) xi[tid] = x_in[orig[tid] * S + t];
        __syncthreads();   // xi ready; prev epilogue hT writes visible

        // init accumulators from input-path table P
        float pl[BT], ph[BT];
#pragma unroll
        for (int b = 0; b < BT; b++) {
            float2 p = __ldg(reinterpret_cast<const float2*>(g_P + xi[b] * H) + tid);
            pl[b] = p.x; ph[b] = p.y;
        }
        unsigned long long a0[BP], a1[BP];
#pragma unroll
        for (int bp = 0; bp < BP; bp++) {
            a0[bp] = pk2(pl[2 * bp], pl[2 * bp + 1]);
            a1[bp] = pk2(ph[2 * bp], ph[2 * bp + 1]);
        }

        gemm_k512(WTu, hT, a0, a1);

        __syncthreads();   // all hT reads complete before overwrite

        float v0[BT], v1[BT];
#pragma unroll
        for (int bp = 0; bp < BP; bp++) {
            float x, y;
            upk2(a0[bp], x, y);
            v0[2 * bp] = tanhf(x); v0[2 * bp + 1] = tanhf(y);
            upk2(a1[bp], x, y);
            v1[2 * bp] = tanhf(x); v1[2 * bp + 1] = tanhf(y);
        }
        // write new h (transposed layout): rows h0 = 2*tid, h1 = 2*tid+1
        hT[(2 * tid) * 2]     = make_ulonglong2(pk2(v0[0], v0[1]), pk2(v0[2], v0[3]));
        hT[(2 * tid) * 2 + 1] = make_ulonglong2(pk2(v0[4], v0[5]), pk2(v0[6], v0[7]));
        hT[(2 * tid + 1) * 2]     = make_ulonglong2(pk2(v1[0], v1[1]), pk2(v1[2], v1[3]));
        hT[(2 * tid + 1) * 2 + 1] = make_ulonglong2(pk2(v1[4], v1[5]), pk2(v1[6], v1[7]));

#pragma unroll
        for (int b = 0; b < BT; b++) {
            if (t == slen[b] - 1) {
                float2 st = make_float2(v0[b], v1[b]);
                reinterpret_cast<float2*>(g_last + orig[b] * H)[tid] = st;
            }
        }
        // next iteration's first __syncthreads orders these writes before reads
    }
}

// ---------------------------------------------------------------------------
// Kernel 5: MLP head. hidden = relu(last @ W1^T + b1); out = hidden @ W2^T + b2
// ---------------------------------------------------------------------------
__global__ void __launch_bounds__(THR) mlp_kernel(const float* __restrict__ b1,
                                                  const float* __restrict__ b2,
                                                  float* __restrict__ out) {
    __shared__ ulonglong2 hT[H * 2];   // transposed input rows, 16 KB
    __shared__ float hlin[BT * H];     // relu'd hidden, row-major, 16 KB

    const int tid  = threadIdx.x;
    const int base = blockIdx.x * BT;

    // load 8 rows of g_last into transposed [k][b] layout
    float* hTf = reinterpret_cast<float*>(hT);
    for (int i = tid; i < BT * H; i += THR) {
        int b = i >> 9, k = i & (H - 1);
        hTf[k * BT + b] = g_last[(base + b) * H + k];
    }
    __syncthreads();

    const unsigned long long* WTu =
        reinterpret_cast<const unsigned long long*>(g_W1T) + tid;

    float b1l = __ldg(b1 + 2 * tid), b1h = __ldg(b1 + 2 * tid + 1);
    unsigned long long a0[BP], a1[BP];
#pragma unroll
    for (int bp = 0; bp < BP; bp++) {
        a0[bp] = pk2(b1l, b1l);
        a1[bp] = pk2(b1h, b1h);
    }

    gemm_k512(WTu, hT, a0, a1);

    // relu -> hlin (row-major [b][h])
#pragma unroll
    for (int bp = 0; bp < BP; bp++) {
        float x, y;
        upk2(a0[bp], x, y);
        float r0e = fmaxf(x, 0.f), r0o = fmaxf(y, 0.f);
        upk2(a1[bp], x, y);
        float r1e = fmaxf(x, 0.f), r1o = fmaxf(y, 0.f);
        reinterpret_cast<float2*>(hlin + (2 * bp) * H)[tid]     = make_float2(r0e, r1e);
        reinterpret_cast<float2*>(hlin + (2 * bp + 1) * H)[tid] = make_float2(r0o, r1o);
    }
    __syncthreads();

    // logits: thread (b = tid>>5, c = tid&31)
    const int b = tid >> 5;
    const int c = tid & 31;
    float acc = __ldg(b2 + c);
    const float* hb = hlin + b * H;
#pragma unroll 4
    for (int k = 0; k < H; k += 4) {
        float4 hv = *reinterpret_cast<const float4*>(hb + k);
        acc += hv.x * __ldg(g_W2T + (k + 0) * C + c);
        acc += hv.y * __ldg(g_W2T + (k + 1) * C + c);
        acc += hv.z * __ldg(g_W2T + (k + 2) * C + c);
        acc += hv.w * __ldg(g_W2T + (k + 3) * C + c);
    }
    out[(base + b) * C + c] = acc;
}

// ---------------------------------------------------------------------------
extern "C" void kernel_launch(void* const* d_in, const int* in_sizes, int n_in,
                              void* d_out, int out_size) {
    const int*   x_in   = (const int*)  d_in[0];
    const int*   x_lens = (const int*)  d_in[1];
    const float* emb    = (const float*)d_in[2];
    const float* W_ih   = (const float*)d_in[3];
    const float* b_ih   = (const float*)d_in[4];
    const float* W_hh   = (const float*)d_in[5];
    // b_hh = d_in[6]
    const float* W1w    = (const float*)d_in[7];
    const float* b1     = (const float*)d_in[8];
    const float* W2w    = (const float*)d_in[9];
    const float* b2     = (const float*)d_in[10];
    float* out = (float*)d_out;

    precompute_P<<<V, H>>>(emb, W_ih, b_ih, (const float*)d_in[6]);
    sort_by_len<<<1, B>>>(x_lens);
    int tgrid = (2 * H * H + C * H + 255) / 256;
    transpose_all<<<tgrid, 256>>>(W_hh, W1w, W2w);
    rnn_kernel<<<NBLK, THR>>>(x_in);
    mlp_kernel<<<NBLK, THR>>>(b1, b2, out);
}

// round 3
// speedup vs baseline: 2.8351x; 1.2570x over previous
#include <cuda_runtime.h>
#include <math.h>

// Problem dims (fixed by the dataset)
#define B 1024
#define S 64
#define E 256
#define H 512
#define V 128
#define C 32

#define BT    8            // batch rows per CTA tile
#define BP    4            // batch pairs (f32x2 packs 2 batch rows)
#define HPAIR 256          // h-pairs
#define NBLK  (B / BT)     // 128 CTAs
#define THR   512          // 2 k-groups x 256 h-pair threads
#define THRM  256          // mlp kernel threads

// Scratch (no allocations allowed -> __device__ globals)
__device__ float  g_P[V * H];                     // emb @ W_ih^T + b_ih + b_hh
__device__ float4 g_Wp[(H / 2) * (H / 2)];        // paired W_hh^T (1 MB)
__device__ float  g_W1T[H * H];                   // W1^T [k][h]
__device__ float  g_W2T[H * C];                   // W2^T [k][c]
__device__ float  g_last[B * H];                  // h at t=len-1, original order
__device__ int    g_sidx[B];
__device__ int    g_slen[B];

// ---------------------------------------------------------------------------
// f32x2 helpers
// ---------------------------------------------------------------------------
typedef unsigned long long ull;
__device__ __forceinline__ ull pk2(float x, float y) {
    ull r; asm("mov.b64 %0, {%1, %2};" : "=l"(r) : "f"(x), "f"(y)); return r;
}
__device__ __forceinline__ void upk2(ull v, float& x, float& y) {
    asm("mov.b64 {%0, %1}, %2;" : "=f"(x), "=f"(y) : "l"(v));
}
__device__ __forceinline__ void fma2(ull& d, ull a, ull b) {
    asm("fma.rn.f32x2 %0, %1, %2, %3;" : "=l"(d) : "l"(a), "l"(b), "l"(d));
}
__device__ __forceinline__ void add2(ull& d, ull a, ull b) {
    asm("add.rn.f32x2 %0, %1, %2;" : "=l"(d) : "l"(a), "l"(b));
}

// ---------------------------------------------------------------------------
// Kernel 1: P[v][h] = sum_e emb[v,e] * W_ih[h,e] + b_ih[h] + b_hh[h]
// ---------------------------------------------------------------------------
__global__ void precompute_P(const float* __restrict__ emb,
                             const float* __restrict__ W_ih,
                             const float* __restrict__ b_ih,
                             const float* __restrict__ b_hh) {
    __shared__ float es[E];
    const int v = blockIdx.x;
    const int h = threadIdx.x;
    if (h < E) es[h] = emb[v * E + h];
    __syncthreads();

    float acc = b_ih[h] + b_hh[h];
    const float4* w  = reinterpret_cast<const float4*>(W_ih + h * E);
    const float4* e4 = reinterpret_cast<const float4*>(es);
#pragma unroll 8
    for (int i = 0; i < E / 4; i++) {
        float4 a = e4[i], b = w[i];
        acc += a.x * b.x + a.y * b.y + a.z * b.z + a.w * b.w;
    }
    g_P[v * H + h] = acc;
}

// ---------------------------------------------------------------------------
// Kernel 2: stable rank sort of rows by length
// ---------------------------------------------------------------------------
__global__ void sort_by_len(const int* __restrict__ lens) {
    __shared__ int sl[B];
    const int i = threadIdx.x;
    sl[i] = lens[i];
    __syncthreads();
    const int my = sl[i];
    int rank = 0;
#pragma unroll 8
    for (int j = 0; j < B; j++) {
        int lj = sl[j];
        rank += (lj < my) || (lj == my && j < i);
    }
    g_sidx[rank] = i;
    g_slen[rank] = my;
}

// ---------------------------------------------------------------------------
// Kernel 3: build paired-k W_hh layout + W1^T + W2^T
// g_Wp[(kp*HPAIR + hp)] = {W[2kp][2hp], W[2kp][2hp+1], W[2kp+1][2hp], W[2kp+1][2hp+1]}
// ---------------------------------------------------------------------------
__global__ void transpose_all(const float* __restrict__ W_hh,
                              const float* __restrict__ W1,
                              const float* __restrict__ W2) {
    int idx = blockIdx.x * blockDim.x + threadIdx.x;
    if (idx < H * H) {
        int h = idx >> 9, k = idx & (H - 1);
        int kp = k >> 1, hp = h >> 1;
        reinterpret_cast<float*>(g_Wp)[(kp * HPAIR + hp) * 4 + (k & 1) * 2 + (h & 1)]
            = W_hh[idx];
    } else if (idx < 2 * H * H) {
        int j = idx - H * H;
        int h = j >> 9, k = j & (H - 1);
        g_W1T[k * H + h] = W1[j];
    } else {
        int j = idx - 2 * H * H;
        if (j < C * H) {
            int c = j >> 9, k = j & (H - 1);
            g_W2T[k * C + c] = W2[j];
        }
    }
}

// ---------------------------------------------------------------------------
// RNN inner compute: 4 kp (8 k) with weights in regs.
// hT2: [k][2] ulonglong2 (batch pairs). a0 = accum for h0, a1 for h1.
// ---------------------------------------------------------------------------
__device__ __forceinline__ void comp4(const ulonglong2* __restrict__ hT2, int k0,
                                      const ulonglong2 w[4], ull a0[BP], ull a1[BP]) {
#pragma unroll
    for (int j = 0; j < 4; j++) {
        const int k = k0 + 2 * j;
        float wl, wh;
        {
            ulonglong2 hA = hT2[k * 2], hB = hT2[k * 2 + 1];
            upk2(w[j].x, wl, wh);
            ull s0 = pk2(wl, wl), s1 = pk2(wh, wh);
            fma2(a0[0], hA.x, s0); fma2(a0[1], hA.y, s0);
            fma2(a0[2], hB.x, s0); fma2(a0[3], hB.y, s0);
            fma2(a1[0], hA.x, s1); fma2(a1[1], hA.y, s1);
            fma2(a1[2], hB.x, s1); fma2(a1[3], hB.y, s1);
        }
        {
            ulonglong2 hA = hT2[(k + 1) * 2], hB = hT2[(k + 1) * 2 + 1];
            upk2(w[j].y, wl, wh);
            ull s0 = pk2(wl, wl), s1 = pk2(wh, wh);
            fma2(a0[0], hA.x, s0); fma2(a0[1], hA.y, s0);
            fma2(a0[2], hB.x, s0); fma2(a0[3], hB.y, s0);
            fma2(a1[0], hA.x, s1); fma2(a1[1], hA.y, s1);
            fma2(a1[2], hB.x, s1); fma2(a1[3], hB.y, s1);
        }
    }
}

// ---------------------------------------------------------------------------
// Kernel 4: persistent RNN, 2-way k-split.
// grp 0: k [0,256) + epilogue (reduce, tanh, state update)
// grp 1: k [256,512), writes partials to smem
// ---------------------------------------------------------------------------
__global__ void __launch_bounds__(THR) rnn_kernel(const int* __restrict__ x_in) {
    __shared__ ulonglong2 hT2[H * 2];       // [k][2] batch-pair state, 16 KB
    __shared__ ulonglong2 pB[HPAIR * 4];    // group-B partials, 16 KB
    __shared__ int orig[BT], slen[BT], xi[BT];

    const int tid  = threadIdx.x;
    const int grp  = tid >> 8;              // 0 or 1
    const int hp   = tid & (HPAIR - 1);
    const int base = blockIdx.x * BT;

    if (tid < BT) {
        orig[tid] = g_sidx[base + tid];
        slen[tid] = g_slen[base + tid];
    }
    for (int i = tid; i < H * 2; i += THR) hT2[i] = make_ulonglong2(0ull, 0ull);
    __syncthreads();

    int tmax = 0;
#pragma unroll
    for (int b = 0; b < BT; b++) tmax = max(tmax, slen[b]);

    // this thread's W column: element (kpl, hp) at Wp[kpl*HPAIR]
    const ulonglong2* Wp =
        reinterpret_cast<const ulonglong2*>(g_Wp) + (grp * 128) * HPAIR + hp;
    const int kbase = grp * 256;            // global k of this group's range

    for (int t = 0; t < tmax; t++) {
        if (tid < BT) xi[tid] = x_in[orig[tid] * S + t];
        __syncthreads();    // (1) xi ready; hT2 from previous epilogue visible

        ull a0[BP], a1[BP];
        if (grp == 0) {
            float pl[BT], ph[BT];
#pragma unroll
            for (int b = 0; b < BT; b++) {
                float2 p = __ldg(reinterpret_cast<const float2*>(g_P + xi[b] * H) + hp);
                pl[b] = p.x; ph[b] = p.y;
            }
#pragma unroll
            for (int bp = 0; bp < BP; bp++) {
                a0[bp] = pk2(pl[2 * bp], pl[2 * bp + 1]);
                a1[bp] = pk2(ph[2 * bp], ph[2 * bp + 1]);
            }
        } else {
#pragma unroll
            for (int bp = 0; bp < BP; bp++) { a0[bp] = 0ull; a1[bp] = 0ull; }
        }

        // 128 kp for this group, 8-kp chunks, double-buffered W prefetch
        ulonglong2 wA[4], wB[4];
#pragma unroll
        for (int j = 0; j < 4; j++) wA[j] = __ldg(Wp + j * HPAIR);
#pragma unroll 1
        for (int c = 0; c < 128; c += 8) {
#pragma unroll
            for (int j = 0; j < 4; j++) wB[j] = __ldg(Wp + (c + 4 + j) * HPAIR);
            comp4(hT2, kbase + 2 * c, wA, a0, a1);
            const int nc = (c + 8) & 127;   // wrap-around dummy on last iter
#pragma unroll
            for (int j = 0; j < 4; j++) wA[j] = __ldg(Wp + (nc + j) * HPAIR);
            comp4(hT2, kbase + 2 * (c + 4), wB, a0, a1);
        }

        if (grp == 1) {
            ulonglong2* dst = pB + hp * 4;
            dst[0] = make_ulonglong2(a0[0], a0[1]);
            dst[1] = make_ulonglong2(a0[2], a0[3]);
            dst[2] = make_ulonglong2(a1[0], a1[1]);
            dst[3] = make_ulonglong2(a1[2], a1[3]);
        }
        __syncthreads();    // (2) partials visible; all hT2 reads complete

        if (grp == 0) {
            const ulonglong2* src = pB + hp * 4;
            ulonglong2 q0 = src[0], q1 = src[1], q2 = src[2], q3 = src[3];
            add2(a0[0], a0[0], q0.x); add2(a0[1], a0[1], q0.y);
            add2(a0[2], a0[2], q1.x); add2(a0[3], a0[3], q1.y);
            add2(a1[0], a1[0], q2.x); add2(a1[1], a1[1], q2.y);
            add2(a1[2], a1[2], q3.x); add2(a1[3], a1[3], q3.y);

            float v0[BT], v1[BT];
#pragma unroll
            for (int bp = 0; bp < BP; bp++) {
                float x, y;
                upk2(a0[bp], x, y);
                v0[2 * bp] = tanhf(x); v0[2 * bp + 1] = tanhf(y);
                upk2(a1[bp], x, y);
                v1[2 * bp] = tanhf(x); v1[2 * bp + 1] = tanhf(y);
            }
            hT2[(2 * hp) * 2] =
                make_ulonglong2(pk2(v0[0], v0[1]), pk2(v0[2], v0[3]));
            hT2[(2 * hp) * 2 + 1] =
                make_ulonglong2(pk2(v0[4], v0[5]), pk2(v0[6], v0[7]));
            hT2[(2 * hp + 1) * 2] =
                make_ulonglong2(pk2(v1[0], v1[1]), pk2(v1[2], v1[3]));
            hT2[(2 * hp + 1) * 2 + 1] =
                make_ulonglong2(pk2(v1[4], v1[5]), pk2(v1[6], v1[7]));

#pragma unroll
            for (int b = 0; b < BT; b++) {
                if (t == slen[b] - 1) {
                    reinterpret_cast<float2*>(g_last + orig[b] * H)[hp] =
                        make_float2(v0[b], v1[b]);
                }
            }
        }
        // next iteration's sync (1) orders the hT2 writes before group-B reads
    }
}

// ---------------------------------------------------------------------------
// MLP helpers (k-major W, unpaired) — as in round 2
// ---------------------------------------------------------------------------
#define HP (H / 2)
__device__ __forceinline__ void load8(const ull* __restrict__ WTu, int k, ull w[8]) {
#pragma unroll
    for (int j = 0; j < 8; j++) w[j] = __ldg(WTu + (unsigned)(k + j) * HP);
}
__device__ __forceinline__ void compute8(const ulonglong2* __restrict__ hT, int k0,
                                         const ull w[8], ull a0[BP], ull a1[BP]) {
#pragma unroll
    for (int j = 0; j < 8; j++) {
        ulonglong2 hA = hT[(k0 + j) * 2];
        ulonglong2 hB = hT[(k0 + j) * 2 + 1];
        float wl, wh;
        upk2(w[j], wl, wh);
        ull s0 = pk2(wl, wl), s1 = pk2(wh, wh);
        fma2(a0[0], hA.x, s0); fma2(a0[1], hA.y, s0);
        fma2(a0[2], hB.x, s0); fma2(a0[3], hB.y, s0);
        fma2(a1[0], hA.x, s1); fma2(a1[1], hA.y, s1);
        fma2(a1[2], hB.x, s1); fma2(a1[3], hB.y, s1);
    }
}
__device__ __forceinline__ void gemm_k512(const ull* __restrict__ WTu,
                                          const ulonglong2* __restrict__ hT,
                                          ull a0[BP], ull a1[BP]) {
    ull wA[8], wB[8];
    load8(WTu, 0, wA);
#pragma unroll 1
    for (int k0 = 0; k0 < H; k0 += 16) {
        load8(WTu, k0 + 8, wB);
        compute8(hT, k0, wA, a0, a1);
        int kn = (k0 + 16 < H) ? k0 + 16 : 0;
        load8(WTu, kn, wA);
        compute8(hT, k0 + 8, wB, a0, a1);
    }
}

// ---------------------------------------------------------------------------
// Kernel 5: MLP head
// ---------------------------------------------------------------------------
__global__ void __launch_bounds__(THRM) mlp_kernel(const float* __restrict__ b1,
                                                   const float* __restrict__ b2,
                                                   float* __restrict__ out) {
    __shared__ ulonglong2 hT[H * 2];
    __shared__ float hlin[BT * H];

    const int tid  = threadIdx.x;
    const int base = blockIdx.x * BT;

    float* hTf = reinterpret_cast<float*>(hT);
    for (int i = tid; i < BT * H; i += THRM) {
        int b = i >> 9, k = i & (H - 1);
        hTf[k * BT + b] = g_last[(base + b) * H + k];
    }
    __syncthreads();

    const ull* WTu = reinterpret_cast<const ull*>(g_W1T) + tid;

    float b1l = __ldg(b1 + 2 * tid), b1h = __ldg(b1 + 2 * tid + 1);
    ull a0[BP], a1[BP];
#pragma unroll
    for (int bp = 0; bp < BP; bp++) {
        a0[bp] = pk2(b1l, b1l);
        a1[bp] = pk2(b1h, b1h);
    }

    gemm_k512(WTu, hT, a0, a1);

#pragma unroll
    for (int bp = 0; bp < BP; bp++) {
        float x, y;
        upk2(a0[bp], x, y);
        float r0e = fmaxf(x, 0.f), r0o = fmaxf(y, 0.f);
        upk2(a1[bp], x, y);
        float r1e = fmaxf(x, 0.f), r1o = fmaxf(y, 0.f);
        reinterpret_cast<float2*>(hlin + (2 * bp) * H)[tid]     = make_float2(r0e, r1e);
        reinterpret_cast<float2*>(hlin + (2 * bp + 1) * H)[tid] = make_float2(r0o, r1o);
    }
    __syncthreads();

    const int b = tid >> 5;
    const int c = tid & 31;
    float acc = __ldg(b2 + c);
    const float* hb = hlin + b * H;
#pragma unroll 4
    for (int k = 0; k < H; k += 4) {
        float4 hv = *reinterpret_cast<const float4*>(hb + k);
        acc += hv.x * __ldg(g_W2T + (k + 0) * C + c);
        acc += hv.y * __ldg(g_W2T + (k + 1) * C + c);
        acc += hv.z * __ldg(g_W2T + (k + 2) * C + c);
        acc += hv.w * __ldg(g_W2T + (k + 3) * C + c);
    }
    out[(base + b) * C + c] = acc;
}

// ---------------------------------------------------------------------------
extern "C" void kernel_launch(void* const* d_in, const int* in_sizes, int n_in,
                              void* d_out, int out_size) {
    const int*   x_in   = (const int*)  d_in[0];
    const int*   x_lens = (const int*)  d_in[1];
    const float* emb    = (const float*)d_in[2];
    const float* W_ih   = (const float*)d_in[3];
    const float* b_ih   = (const float*)d_in[4];
    const float* W_hh   = (const float*)d_in[5];
    const float* b_hh   = (const float*)d_in[6];
    const float* W1w    = (const float*)d_in[7];
    const float* b1     = (const float*)d_in[8];
    const float* W2w    = (const float*)d_in[9];
    const float* b2     = (const float*)d_in[10];
    float* out = (float*)d_out;

    precompute_P<<<V, H>>>(emb, W_ih, b_ih, b_hh);
    sort_by_len<<<1, B>>>(x_lens);
    int tgrid = (2 * H * H + C * H + 255) / 256;
    transpose_all<<<tgrid, 256>>>(W_hh, W1w, W2w);
    rnn_kernel<<<NBLK, THR>>>(x_in);
    mlp_kernel<<<NBLK, THRM>>>(b1, b2, out);
}